// round 4
// baseline (speedup 1.0000x reference)
#include <cuda_runtime.h>
#include <math.h>

// Problem constants (fixed shapes from reference)
#define BB 2
#define CC 64
#define DD 64
#define HH 128
#define WW 128
#define HW (HH * WW)          // 16384
#define BC (BB * CC)          // 128
#define SLAB ((size_t)DD * HW) // 1,048,576 elements per (b,c)
#define NTH 512               // threads per CTA (16 warps)
#define TH 8                  // output rows per thread
#define SMEM_BYTES (3 * HW * sizeof(float)) // 196608 B (3 planes)
#define EPS 1e-5f

// Deterministic two-stage reduction scratch (static device globals: allowed)
__device__ float g_psum[BC * DD];
__device__ float g_psq[BC * DD];
__device__ float g_mean[BC];
__device__ float g_rstd[BC];

// PASS 1: conv + per-CTA (sum, sumsq) partials.
// PASS 2: conv recompute + normalize + relu + store.
template <int PASS>
__global__ __launch_bounds__(NTH) void dwconv_kernel(
    const float* __restrict__ x,
    const float* __restrict__ wt,
    const float* __restrict__ gamma,
    const float* __restrict__ beta,
    float* __restrict__ out)
{
    extern __shared__ float sm[];  // 3 planes of HxW
    const int d  = blockIdx.x;
    const int bc = blockIdx.y;
    const int c  = bc & (CC - 1);
    const float* xs = x + (size_t)bc * SLAB;
    const int tid = threadIdx.x;

    // ---- Stage 3 input planes (d-1, d, d+1) into SMEM, zero-fill at D edges ----
    #pragma unroll
    for (int dz = 0; dz < 3; ++dz) {
        const int zp = d - 1 + dz;
        float4* dst = (float4*)(sm + dz * HW);
        if ((unsigned)zp < (unsigned)DD) {
            const float4* src = (const float4*)(xs + (size_t)zp * HW);
            #pragma unroll
            for (int i = 0; i < HW / 4 / NTH; ++i)
                dst[tid + i * NTH] = src[tid + i * NTH];
        } else {
            const float4 z = make_float4(0.f, 0.f, 0.f, 0.f);
            #pragma unroll
            for (int i = 0; i < HW / 4 / NTH; ++i)
                dst[tid + i * NTH] = z;
        }
    }

    // ---- Per-channel 3x3x3 weights into registers (compile-time indexed) ----
    float wr[27];
    #pragma unroll
    for (int i = 0; i < 27; ++i) wr[i] = __ldg(wt + c * 27 + i);

    __syncthreads();

    const int lane = tid & 31;
    const int warp = tid >> 5;
    const int w0 = lane << 2;   // warp's 32 lanes tile the full W=128 row
    const int h0 = warp * TH;   // 16 warps * 8 rows = 128 rows

    float acc[TH][4];
    #pragma unroll
    for (int o = 0; o < TH; ++o)
        #pragma unroll
        for (int j = 0; j < 4; ++j) acc[o][j] = 0.f;

    #pragma unroll
    for (int dz = 0; dz < 3; ++dz) {
        const float* pl = sm + dz * HW;
        #pragma unroll
        for (int r = 0; r < TH + 2; ++r) {
            const int hhh = h0 - 1 + r;
            if (hhh < 0 || hhh >= HH) continue;  // H zero-pad (uniform per warp)

            const float4 Bv = *(const float4*)(pl + hhh * WW + w0);
            // W-halo via shuffles; lane 0/31 masking == true zero padding
            float left  = __shfl_up_sync(0xffffffffu, Bv.w, 1);
            if (lane == 0) left = 0.f;
            float right = __shfl_down_sync(0xffffffffu, Bv.x, 1);
            if (lane == 31) right = 0.f;

            const float v0 = left, v1 = Bv.x, v2 = Bv.y, v3 = Bv.z, v4 = Bv.w, v5 = right;
            const float v[6] = {v0, v1, v2, v3, v4, v5};

            #pragma unroll
            for (int o = 0; o < TH; ++o) {
                const int dy = r - o;               // input row hhh used with tap dy
                if (dy < 0 || dy > 2) continue;     // folds at compile time
                const float W0 = wr[dz * 9 + dy * 3 + 0];
                const float W1 = wr[dz * 9 + dy * 3 + 1];
                const float W2 = wr[dz * 9 + dy * 3 + 2];
                #pragma unroll
                for (int j = 0; j < 4; ++j) {
                    acc[o][j] = fmaf(v[j],     W0,
                                fmaf(v[j + 1], W1,
                                fmaf(v[j + 2], W2, acc[o][j])));
                }
            }
        }
    }

    if (PASS == 1) {
        // Deterministic block reduction of sum / sumsq
        float s = 0.f, sq = 0.f;
        #pragma unroll
        for (int o = 0; o < TH; ++o)
            #pragma unroll
            for (int j = 0; j < 4; ++j) {
                const float yv = acc[o][j];
                s += yv;
                sq = fmaf(yv, yv, sq);
            }
        #pragma unroll
        for (int off = 16; off > 0; off >>= 1) {
            s  += __shfl_down_sync(0xffffffffu, s, off);
            sq += __shfl_down_sync(0xffffffffu, sq, off);
        }
        __syncthreads();  // everyone done reading planes; safe to reuse sm
        if (lane == 0) { sm[warp] = s; sm[32 + warp] = sq; }
        __syncthreads();
        if (warp == 0) {
            float a  = (lane < NTH / 32) ? sm[lane] : 0.f;
            float aq = (lane < NTH / 32) ? sm[32 + lane] : 0.f;
            #pragma unroll
            for (int off = 16; off > 0; off >>= 1) {
                a  += __shfl_down_sync(0xffffffffu, a, off);
                aq += __shfl_down_sync(0xffffffffu, aq, off);
            }
            if (lane == 0) {
                g_psum[bc * DD + d] = a;
                g_psq[bc * DD + d]  = aq;
            }
        }
    } else {
        // Normalize + ReLU + store (fused affine: y*g + b)
        const float rstd = g_rstd[bc];
        const float mean = g_mean[bc];
        const float gsc  = gamma[c] * rstd;
        const float bsc  = fmaf(-mean, gsc, beta[c]);
        float* os = out + (size_t)bc * SLAB + (size_t)d * HW;
        #pragma unroll
        for (int o = 0; o < TH; ++o) {
            float4 r4;
            r4.x = fmaxf(fmaf(acc[o][0], gsc, bsc), 0.f);
            r4.y = fmaxf(fmaf(acc[o][1], gsc, bsc), 0.f);
            r4.z = fmaxf(fmaf(acc[o][2], gsc, bsc), 0.f);
            r4.w = fmaxf(fmaf(acc[o][3], gsc, bsc), 0.f);
            *(float4*)(os + (h0 + o) * WW + w0) = r4;
        }
    }
}

// Finalize mean / rstd per (b,c). Fully deterministic (sequential adds).
__global__ void finalize_stats_kernel()
{
    const int bc = threadIdx.x;
    if (bc >= BC) return;
    double s = 0.0, sq = 0.0;
    #pragma unroll 4
    for (int d = 0; d < DD; ++d) {
        s  += (double)g_psum[bc * DD + d];
        sq += (double)g_psq[bc * DD + d];
    }
    const double n = (double)SLAB;
    const double mean = s / n;
    const double var  = sq / n - mean * mean;
    g_mean[bc] = (float)mean;
    g_rstd[bc] = (float)(1.0 / sqrt(var + (double)EPS));
}

extern "C" void kernel_launch(void* const* d_in, const int* in_sizes, int n_in,
                              void* d_out, int out_size)
{
    (void)in_sizes; (void)n_in; (void)out_size;
    const float* x     = (const float*)d_in[0];
    const float* w     = (const float*)d_in[1];
    const float* gamma = (const float*)d_in[2];
    const float* beta  = (const float*)d_in[3];
    float* out = (float*)d_out;

    cudaFuncSetAttribute(dwconv_kernel<1>,
                         cudaFuncAttributeMaxDynamicSharedMemorySize, SMEM_BYTES);
    cudaFuncSetAttribute(dwconv_kernel<2>,
                         cudaFuncAttributeMaxDynamicSharedMemorySize, SMEM_BYTES);

    dim3 grid(DD, BC);  // x = d (adjacent-d CTAs co-scheduled -> L2 plane reuse), y = bc
    dwconv_kernel<1><<<grid, NTH, SMEM_BYTES>>>(x, w, gamma, beta, out);
    finalize_stats_kernel<<<1, BC>>>();
    dwconv_kernel<2><<<grid, NTH, SMEM_BYTES>>>(x, w, gamma, beta, out);
}

// round 6
// speedup vs baseline: 1.7691x; 1.7691x over previous
#include <cuda_runtime.h>
#include <math.h>

#define DD    64
#define HH    128
#define WW    128
#define HW    (HH * WW)            // 16384
#define BC    128
#define CCH   64
#define SLAB  ((size_t)DD * HW)    // 1,048,576 per (b,c)
#define NTHR  128                  // 4 warps; warp covers W=128 (float4/lane), 8 rows
#define NCHUNK 4                   // H split into 4 chunks of 32 rows
#define LROWS 34                   // 32 output rows + 2 halo rows
#define ROW_F4 (WW / 4)            // 32 float4 per row
#define PLANE_F4 (LROWS * ROW_F4)  // 1088 float4 per tile-plane
#define SMEM_BYTES (3 * PLANE_F4 * 16)  // 52224 B (3-buffer ring)

typedef unsigned long long u64;

__device__ float g_psum[BC * NCHUNK];
__device__ float g_psq [BC * NCHUNK];
__device__ float g_mean[BC];
__device__ float g_rstd[BC];

// ---- packed fp32x2 helpers (Blackwell f32x2 pipe: 2x FFMA throughput vs 3-reg FFMA) ----
__device__ __forceinline__ u64 pk2(float lo, float hi) {
    u64 r;
    asm("mov.b64 %0, {%1, %2};" : "=l"(r)
        : "r"(__float_as_uint(lo)), "r"(__float_as_uint(hi)));
    return r;
}
__device__ __forceinline__ void upk2(u64 v, float& lo, float& hi) {
    unsigned int a, b;
    asm("mov.b64 {%0, %1}, %2;" : "=r"(a), "=r"(b) : "l"(v));
    lo = __uint_as_float(a); hi = __uint_as_float(b);
}
__device__ __forceinline__ void fma2i(u64& acc, u64 a, u64 b) {
    asm("fma.rn.f32x2 %0, %1, %2, %0;" : "+l"(acc) : "l"(a), "l"(b));
}
__device__ __forceinline__ u64 fma2o(u64 a, u64 b, u64 c) {
    u64 d;
    asm("fma.rn.f32x2 %0, %1, %2, %3;" : "=l"(d) : "l"(a), "l"(b), "l"(c));
    return d;
}
__device__ __forceinline__ void add2i(u64& acc, u64 a) {
    asm("add.rn.f32x2 %0, %1, %0;" : "+l"(acc) : "l"(a));
}

// ---- async tile-plane load: 34 rows x 128 cols, zero-filled at H edges ----
__device__ __forceinline__ void load_plane(const float* __restrict__ xs, int z, int h0,
                                           float4* __restrict__ buf, int tid)
{
    const float* src = xs + (size_t)z * HW;
    unsigned int sbase = (unsigned int)__cvta_generic_to_shared(buf);
    #pragma unroll
    for (int it = 0; it < 9; ++it) {
        int i = tid + it * NTHR;
        if (it < 8 || i < PLANE_F4) {
            int row = i >> 5;
            int c4  = i & 31;
            int h   = h0 - 1 + row;
            if ((unsigned)h < (unsigned)HH) {
                const float* g = src + h * WW + c4 * 4;
                unsigned int sa = sbase + i * 16;
                asm volatile("cp.async.cg.shared.global [%0], [%1], 16;"
                             :: "r"(sa), "l"(g));
            } else {
                buf[i] = make_float4(0.f, 0.f, 0.f, 0.f);  // H zero-pad
            }
        }
    }
}
__device__ __forceinline__ void commit_g() {
    asm volatile("cp.async.commit_group;" ::: "memory");
}

// ---- one sweep over the 10 smem rows a warp needs; updates 1 or 2 acc targets ----
// Target A gets weight slice SA, target B gets slice SB (compile-time -> reg-indexed Wp).
template<int NT, int SA, int SB>
__device__ __forceinline__ void conv_pass(const float4* __restrict__ buf, int olb, int lane,
                                          const u64 (&Wp)[27], u64 (&A)[16], u64 (&B)[16])
{
    #pragma unroll
    for (int r = 0; r < 10; ++r) {
        float4 q = buf[(olb + r) * ROW_F4 + lane];
        float left  = __shfl_up_sync(0xffffffffu, q.w, 1);
        float right = __shfl_down_sync(0xffffffffu, q.x, 1);
        if (lane == 0)  left  = 0.f;   // true W zero-pad
        if (lane == 31) right = 0.f;
        u64 pp[5];
        pp[0] = pk2(left, q.x);
        pp[1] = pk2(q.x,  q.y);
        pp[2] = pk2(q.y,  q.z);
        pp[3] = pk2(q.z,  q.w);
        pp[4] = pk2(q.w,  right);
        #pragma unroll
        for (int oo = 0; oo < 8; ++oo) {
            const int dy = r - oo;
            if (dy < 0 || dy > 2) continue;      // folds at compile time
            {
                const u64 w0 = Wp[SA * 9 + dy * 3 + 0];
                const u64 w1 = Wp[SA * 9 + dy * 3 + 1];
                const u64 w2 = Wp[SA * 9 + dy * 3 + 2];
                fma2i(A[oo * 2 + 0], pp[0], w0);
                fma2i(A[oo * 2 + 0], pp[1], w1);
                fma2i(A[oo * 2 + 0], pp[2], w2);
                fma2i(A[oo * 2 + 1], pp[2], w0);
                fma2i(A[oo * 2 + 1], pp[3], w1);
                fma2i(A[oo * 2 + 1], pp[4], w2);
            }
            if (NT == 2) {
                const u64 w0 = Wp[SB * 9 + dy * 3 + 0];
                const u64 w1 = Wp[SB * 9 + dy * 3 + 1];
                const u64 w2 = Wp[SB * 9 + dy * 3 + 2];
                fma2i(B[oo * 2 + 0], pp[0], w0);
                fma2i(B[oo * 2 + 0], pp[1], w1);
                fma2i(B[oo * 2 + 0], pp[2], w2);
                fma2i(B[oo * 2 + 1], pp[2], w0);
                fma2i(B[oo * 2 + 1], pp[3], w1);
                fma2i(B[oo * 2 + 1], pp[4], w2);
            }
        }
    }
}

// ---- finalize a completed output plane: stats (pass1) or normalize+relu+store (pass2) ----
template<int PASS>
__device__ __forceinline__ void finalize(u64 (&A)[16], int d, u64& s2, u64& q2,
                                         u64 gsc2, u64 bsc2, float* __restrict__ outp)
{
    if (PASS == 1) {
        #pragma unroll
        for (int i = 0; i < 16; ++i) { add2i(s2, A[i]); fma2i(q2, A[i], A[i]); }
    } else {
        float* os = outp + (size_t)d * HW;
        #pragma unroll
        for (int oo = 0; oo < 8; ++oo) {
            u64 ya = fma2o(A[oo * 2 + 0], gsc2, bsc2);
            u64 yb = fma2o(A[oo * 2 + 1], gsc2, bsc2);
            float a0, a1, a2, a3;
            upk2(ya, a0, a1); upk2(yb, a2, a3);
            float4 r4;
            r4.x = fmaxf(a0, 0.f); r4.y = fmaxf(a1, 0.f);
            r4.z = fmaxf(a2, 0.f); r4.w = fmaxf(a3, 0.f);
            *(float4*)(os + oo * WW) = r4;
        }
    }
}

template<int PASS>
__device__ __forceinline__ void full_step(int z, const float* __restrict__ xs,
        float4* __restrict__ smem4, int h0, int tid, int olb, int lane,
        const u64 (&Wp)[27], u64 (&O)[16], u64 (&N)[16],
        u64& s2, u64& q2, u64 gsc2, u64 bsc2, float* __restrict__ outp)
{
    asm volatile("cp.async.wait_group 1;" ::: "memory");  // plane z resident
    __syncthreads();
    const int zp = z + 2;
    if (zp < DD) load_plane(xs, zp, h0, smem4 + (zp % 3) * PLANE_F4, tid);
    commit_g();  // one group per step (possibly empty) keeps the count invariant
    const float4* buf = smem4 + (z % 3) * PLANE_F4;
    conv_pass<2, 2, 1>(buf, olb, lane, Wp, O, N);   // O=out[z-1]+=W2, N=out[z]+=W1
    finalize<PASS>(O, z - 1, s2, q2, gsc2, bsc2, outp);
    #pragma unroll
    for (int i = 0; i < 16; ++i) O[i] = 0ull;
    conv_pass<1, 0, 0>(buf, olb, lane, Wp, O, O);   // O=out[z+1] = W0 contribution
}

// PASS 1: streaming conv + per-CTA (sum, sumsq).  PASS 2: streaming conv + norm + relu + store.
template<int PASS>
__global__ void __launch_bounds__(NTHR, 3)
conv_stream_kernel(const float* __restrict__ x, const float* __restrict__ wt,
                   const float* __restrict__ gamma, const float* __restrict__ beta,
                   float* __restrict__ out)
{
    extern __shared__ float4 smem4[];
    const int hc = blockIdx.x;
    const int bc = blockIdx.y;
    const int c  = bc & (CCH - 1);
    const int h0 = hc * 32;
    const int tid  = threadIdx.x;
    const int lane = tid & 31;
    const int olb  = (tid >> 5) * 8;               // warp's 8 output rows within the chunk
    const float* xs = x + (size_t)bc * SLAB;

    u64 Wp[27];
    #pragma unroll
    for (int i = 0; i < 27; ++i) { float wv = __ldg(wt + c * 27 + i); Wp[i] = pk2(wv, wv); }

    u64 gsc2 = 0, bsc2 = 0;
    float* outp = out + (size_t)bc * SLAB + (size_t)(h0 + olb) * WW + lane * 4;
    if (PASS == 2) {
        const float rstd = g_rstd[bc], mean = g_mean[bc];
        const float gsc = gamma[c] * rstd;
        const float bsc = fmaf(-mean, gsc, beta[c]);
        gsc2 = pk2(gsc, gsc);
        bsc2 = pk2(bsc, bsc);
    }

    // pipeline prologue: planes 0 and 1 in flight
    load_plane(xs, 0, h0, smem4,            tid); commit_g();
    load_plane(xs, 1, h0, smem4 + PLANE_F4, tid); commit_g();

    u64 P[16], Q[16];
    #pragma unroll
    for (int i = 0; i < 16; ++i) { P[i] = 0ull; Q[i] = 0ull; }
    u64 s2 = 0ull, q2 = 0ull;  // bits of (0.f, 0.f)

    // z = 0 (plane -1 is zero -> no W2 target yet): Q=out[0]+=W1, P=out[1]=W0
    asm volatile("cp.async.wait_group 1;" ::: "memory");
    __syncthreads();
    load_plane(xs, 2, h0, smem4 + 2 * PLANE_F4, tid); commit_g();
    conv_pass<2, 1, 0>(smem4, olb, lane, Wp, Q, P);

    for (int zz = 1; zz < 63; zz += 2) {
        full_step<PASS>(zz,     xs, smem4, h0, tid, olb, lane, Wp, Q, P, s2, q2, gsc2, bsc2, outp);
        full_step<PASS>(zz + 1, xs, smem4, h0, tid, olb, lane, Wp, P, Q, s2, q2, gsc2, bsc2, outp);
    }

    // z = 63 (plane 64 is zero): Q=out[62]+=W2, P=out[63]+=W1; both complete
    asm volatile("cp.async.wait_group 0;" ::: "memory");
    __syncthreads();
    conv_pass<2, 2, 1>(smem4 + (63 % 3) * PLANE_F4, olb, lane, Wp, Q, P);
    finalize<PASS>(Q, 62, s2, q2, gsc2, bsc2, outp);
    finalize<PASS>(P, 63, s2, q2, gsc2, bsc2, outp);

    if (PASS == 1) {
        float sl, sh, ql, qh;
        upk2(s2, sl, sh); upk2(q2, ql, qh);
        float s = sl + sh, q = ql + qh;
        #pragma unroll
        for (int off = 16; off > 0; off >>= 1) {
            s += __shfl_down_sync(0xffffffffu, s, off);
            q += __shfl_down_sync(0xffffffffu, q, off);
        }
        __syncthreads();                 // compute done; smem reusable
        float* red = (float*)smem4;
        const int warp = tid >> 5;
        if (lane == 0) { red[warp] = s; red[8 + warp] = q; }
        __syncthreads();
        if (tid == 0) {
            float ss = red[0] + red[1] + red[2] + red[3];
            float qq = red[8] + red[9] + red[10] + red[11];
            g_psum[bc * NCHUNK + hc] = ss;
            g_psq [bc * NCHUNK + hc] = qq;
        }
    }
}

__global__ void finalize_stats_kernel()
{
    const int bc = threadIdx.x;
    if (bc >= BC) return;
    double s = 0.0, q = 0.0;
    #pragma unroll
    for (int j = 0; j < NCHUNK; ++j) {
        s += (double)g_psum[bc * NCHUNK + j];
        q += (double)g_psq [bc * NCHUNK + j];
    }
    const double n = (double)SLAB;
    const double mean = s / n;
    const double var  = q / n - mean * mean;
    g_mean[bc] = (float)mean;
    g_rstd[bc] = (float)(1.0 / sqrt(var + 1e-5));
}

extern "C" void kernel_launch(void* const* d_in, const int* in_sizes, int n_in,
                              void* d_out, int out_size)
{
    (void)in_sizes; (void)n_in; (void)out_size;
    const float* x     = (const float*)d_in[0];
    const float* w     = (const float*)d_in[1];
    const float* gamma = (const float*)d_in[2];
    const float* beta  = (const float*)d_in[3];
    float* out = (float*)d_out;

    cudaFuncSetAttribute(conv_stream_kernel<1>,
                         cudaFuncAttributeMaxDynamicSharedMemorySize, SMEM_BYTES);
    cudaFuncSetAttribute(conv_stream_kernel<2>,
                         cudaFuncAttributeMaxDynamicSharedMemorySize, SMEM_BYTES);

    dim3 grid(NCHUNK, BC);  // 512 CTAs, target 3 CTAs/SM
    conv_stream_kernel<1><<<grid, NTHR, SMEM_BYTES>>>(x, w, gamma, beta, out);
    finalize_stats_kernel<<<1, BC>>>();
    conv_stream_kernel<2><<<grid, NTHR, SMEM_BYTES>>>(x, w, gamma, beta, out);
}